// round 6
// baseline (speedup 1.0000x reference)
#include <cuda_runtime.h>
#include <cuda_bf16.h>

#define S_ 64
#define B_ 64
#define V_ 10000
#define E_ 256
#define H_ 512

// ---------------- device scratch (static: no allocations allowed) ----------------
__device__ float g_h0[B_ * H_];          // current-step layer-0 hidden
__device__ float g_y0[B_ * H_];          // current-step layer-0 output (y0 = Wy0 h0 + by0)
__device__ float g_h1all[S_ * B_ * H_];  // all layer-1 hiddens (feeds logits GEMM)
__device__ unsigned g_bar_cnt;
__device__ unsigned g_bar_gen;

// ---------------- XLA/Eigen fast-tanh clone (bit-emulation of the reference) --------
// XLA:CPU lowers jnp.tanh(f32) to the classic rational approximation (same coeffs as
// Eigen's generic_fast_tanh_float), NOT libm tanh. The recurrence amplifies any
// systematic per-step difference by ~2e4, so we must use the SAME approximation.
__device__ __forceinline__ float tanh_xla(float x)
{
    if (fabsf(x) < 0.0004f) return x;            // XLA tiny-x shortcut
    float xc = fminf(fmaxf(x, -9.0f), 9.0f);     // clamp (irrelevant for |x|<~5 data)
    float x2 = xc * xc;
    float a = -2.76076847742355e-16f;            // alpha_13
    a = __fmaf_rn(a, x2, 2.00018790482477e-13f); // alpha_11
    a = __fmaf_rn(a, x2, -8.60467152213735e-11f);// alpha_9
    a = __fmaf_rn(a, x2, 5.12229709037114e-08f); // alpha_7
    a = __fmaf_rn(a, x2, 1.48572235717979e-05f); // alpha_5
    a = __fmaf_rn(a, x2, 6.37261928875436e-04f); // alpha_3
    a = __fmaf_rn(a, x2, 4.89352455891786e-03f); // alpha_1
    float num = xc * a;
    float q = 1.19825839466702e-06f;             // beta_6
    q = __fmaf_rn(q, x2, 1.18534705686654e-04f); // beta_4
    q = __fmaf_rn(q, x2, 2.26843463243900e-03f); // beta_2
    q = __fmaf_rn(q, x2, 4.89352518554385e-03f); // beta_0
    return __fdiv_rn(num, q);                    // IEEE divide (immune to fast-math)
}

// ---------------- software grid barrier (all 128 CTAs co-resident on 148 SMs) ----------
__device__ __forceinline__ void grid_bar()
{
    __syncthreads();
    if (threadIdx.x == 0) {
        __threadfence();
        unsigned n = gridDim.x;
        unsigned ticket = atomicAdd(&g_bar_cnt, 1u) + 1u;
        unsigned target = (ticket + n - 1u) / n;
        if (ticket % n == 0u) {
            atomicExch(&g_bar_gen, target);
        } else {
            while (atomicAdd(&g_bar_gen, 0u) < target) { }
        }
        __threadfence();
    }
    __syncthreads();
}

__global__ void init_bar_kernel()
{
    g_bar_cnt = 0u;
    g_bar_gen = 0u;
}

// ---------------- recurrence: persistent kernel, 128 CTAs x 256 threads ----------------
// CTA bx owns output columns [bx*4, bx*4+4); thread = (b in 0..63) x (cj in 0..3).
// seg_dot: EXACT Eigen-order dot product: single fp32 accumulator starting at 0,
// k strictly ascending, one __fmaf_rn per term (matches NEON FMLA gebp microkernel).
// SMEM staging is rounding-free (fp32 copies); chunks processed in ascending k.
__device__ __forceinline__ float seg_dot(
    const float* x, const float* emb_g, const float* __restrict__ wmat,
    int len, int colbase, float (*Xs)[65], float (*Ws)[64], const int* sb,
    int b, int cj)
{
    int tid = threadIdx.x;
    float acc = 0.f;
    for (int kk = 0; kk < len; kk += 64) {
        __syncthreads();
#pragma unroll
        for (int i = 0; i < 16; i++) {
            int e = tid + i * 256;
            int bb = e >> 6;
            int k  = e & 63;
            float v;
            if (x) v = x[(size_t)bb * H_ + kk + k];
            else   v = emb_g[(size_t)sb[bb] + kk + k];
            Xs[bb][k] = v;
        }
        {
            int c = tid >> 6;
            int k = tid & 63;
            Ws[c][k] = wmat[(size_t)(colbase + c) * len + kk + k];
        }
        __syncthreads();
        // strict sequential-k fma chain (DO NOT split into partial sums)
#pragma unroll
        for (int k = 0; k < 64; k++) {
            acc = __fmaf_rn(Xs[b][k], Ws[cj][k], acc);
        }
    }
    return acc;
}

__global__ __launch_bounds__(256) void recur_kernel(
    const int* __restrict__ inputs, const float* __restrict__ hidden,
    const float* __restrict__ emb,
    const float* __restrict__ Wx0, const float* __restrict__ Wh0,
    const float* __restrict__ bh0,
    const float* __restrict__ Wy0, const float* __restrict__ by0,
    const float* __restrict__ Wx1, const float* __restrict__ Wh1,
    const float* __restrict__ bh1,
    float* __restrict__ out)
{
    __shared__ float Xs[64][65];
    __shared__ float Ws[4][64];
    __shared__ int sb[64];
    int tid = threadIdx.x;
    int b = tid & 63;
    int cj = tid >> 6;
    int colbase = blockIdx.x * 4;
    int col = colbase + cj;
    float* out_states = out + (size_t)S_ * B_ * V_;

    for (int t = 0; t < S_; t++) {
        if (tid < 64) sb[tid] = inputs[t * B_ + tid] * E_;

        // ---- phase 1: h0 = tanh((emb_t@Wx0^T + p0@Wh0^T) + bh0)  [reference add order]
        float d1 = seg_dot(nullptr, emb, Wx0, E_, colbase, Xs, Ws, sb, b, cj);
        const float* P0 = (t == 0) ? hidden : (g_h1all + (size_t)(t - 1) * B_ * H_);
        float d2 = seg_dot(P0, nullptr, Wh0, H_, colbase, Xs, Ws, sb, b, cj);
        float h0v = tanh_xla((d1 + d2) + bh0[col]);
        g_h0[(size_t)b * H_ + col] = h0v;
        if (t == S_ - 1) out_states[(size_t)b * H_ + col] = h0v;
        grid_bar();

        // ---- phase 2: y0 = h0@Wy0^T + by0  (dot then bias, reference order)
        float dy = seg_dot(g_h0, nullptr, Wy0, H_, colbase, Xs, Ws, sb, b, cj);
        g_y0[(size_t)b * H_ + col] = dy + by0[col];
        grid_bar();

        // ---- phase 3: h1 = tanh((y0@Wx1^T + p1@Wh1^T) + bh1)
        //      p1 = hidden[1] at t=0, else h0 of the CURRENT step (per source forward()).
        float e1 = seg_dot(g_y0, nullptr, Wx1, H_, colbase, Xs, Ws, sb, b, cj);
        const float* P1 = (t == 0) ? (hidden + (size_t)B_ * H_) : g_h0;
        float e2 = seg_dot(P1, nullptr, Wh1, H_, colbase, Xs, Ws, sb, b, cj);
        float h1v = tanh_xla((e1 + e2) + bh1[col]);
        g_h1all[(size_t)t * B_ * H_ + (size_t)b * H_ + col] = h1v;
        if (t == S_ - 1) out_states[(size_t)B_ * H_ + (size_t)b * H_ + col] = h1v;
        grid_bar();
    }
}

// ---------------- logits: C[4096,10000] = H1all[4096,512] @ Wy1[10000,512]^T + by1 ----
// Per-element: single fp32 accumulator, k ascending, fma per term (ptxas contracts
// a*b+acc to FFMA), bias added last -> same rounding sequence as the reference's
// per-timestep Eigen dot + bias add.
__global__ __launch_bounds__(256) void gemm_logits_kernel(
    const float* __restrict__ Bw, const float* __restrict__ bias,
    float* __restrict__ C)
{
    const int Kd = H_;
    const int N  = V_;
    const float* A = g_h1all;
    __shared__ float As[16][132];
    __shared__ float Bs[16][132];
    int tid = threadIdx.x;
    int m0 = blockIdx.y * 128;
    int n0 = blockIdx.x * 128;
    int tm = tid >> 4;
    int tn = tid & 15;
    float acc[8][8];
#pragma unroll
    for (int i = 0; i < 8; i++)
#pragma unroll
        for (int j = 0; j < 8; j++) acc[i][j] = 0.f;

    for (int kk = 0; kk < Kd; kk += 16) {
#pragma unroll
        for (int i = 0; i < 2; i++) {
            int fi = tid + i * 256;
            int row = fi >> 2, seg = fi & 3;
            float4 v = *(const float4*)(A + (size_t)(m0 + row) * Kd + kk + seg * 4);
            As[seg * 4 + 0][row] = v.x; As[seg * 4 + 1][row] = v.y;
            As[seg * 4 + 2][row] = v.z; As[seg * 4 + 3][row] = v.w;
        }
#pragma unroll
        for (int i = 0; i < 2; i++) {
            int fi = tid + i * 256;
            int row = fi >> 2, seg = fi & 3;
            int n = n0 + row;
            float4 v = make_float4(0.f, 0.f, 0.f, 0.f);
            if (n < N) v = *(const float4*)(Bw + (size_t)n * Kd + kk + seg * 4);
            Bs[seg * 4 + 0][row] = v.x; Bs[seg * 4 + 1][row] = v.y;
            Bs[seg * 4 + 2][row] = v.z; Bs[seg * 4 + 3][row] = v.w;
        }
        __syncthreads();
#pragma unroll
        for (int k = 0; k < 16; k++) {   // k strictly ascending; one fma per element
            float4 a0 = *(const float4*)&As[k][tm * 4];
            float4 a1 = *(const float4*)&As[k][tm * 4 + 64];
            float4 b0 = *(const float4*)&Bs[k][tn * 4];
            float4 b1 = *(const float4*)&Bs[k][tn * 4 + 64];
            float av[8] = {a0.x, a0.y, a0.z, a0.w, a1.x, a1.y, a1.z, a1.w};
            float bv[8] = {b0.x, b0.y, b0.z, b0.w, b1.x, b1.y, b1.z, b1.w};
#pragma unroll
            for (int i = 0; i < 8; i++)
#pragma unroll
                for (int j = 0; j < 8; j++)
                    acc[i][j] = __fmaf_rn(av[i], bv[j], acc[i][j]);
        }
        __syncthreads();
    }

#pragma unroll
    for (int i = 0; i < 8; i++) {
        int m = m0 + ((i < 4) ? (tm * 4 + i) : (64 + tm * 4 + i - 4));
#pragma unroll
        for (int jq = 0; jq < 2; jq++) {
            int c0 = n0 + tn * 4 + jq * 64;
            if (c0 < N) {
                float4 o;
                o.x = acc[i][jq * 4 + 0] + bias[c0 + 0];
                o.y = acc[i][jq * 4 + 1] + bias[c0 + 1];
                o.z = acc[i][jq * 4 + 2] + bias[c0 + 2];
                o.w = acc[i][jq * 4 + 3] + bias[c0 + 3];
                *(float4*)(C + (size_t)m * N + c0) = o;
            }
        }
    }
}

// ---------------- launch ----------------
extern "C" void kernel_launch(void* const* d_in, const int* in_sizes, int n_in,
                              void* d_out, int out_size)
{
    const int*   inputs = (const int*)d_in[0];
    const float* hidden = (const float*)d_in[1];
    const float* emb    = (const float*)d_in[2];
    const float* Wx0    = (const float*)d_in[3];
    const float* Wh0    = (const float*)d_in[4];
    const float* bh0    = (const float*)d_in[5];
    const float* Wy0    = (const float*)d_in[6];
    const float* by0    = (const float*)d_in[7];
    const float* Wx1    = (const float*)d_in[8];
    const float* Wh1    = (const float*)d_in[9];
    const float* bh1    = (const float*)d_in[10];
    const float* Wy1    = (const float*)d_in[11];
    const float* by1    = (const float*)d_in[12];
    float* out = (float*)d_out;

    (void)in_sizes; (void)n_in; (void)out_size;

    // 1) reset grid barrier (required for every graph replay)
    init_bar_kernel<<<1, 1>>>();
    // 2) sequential recurrence, bit-emulating XLA:CPU/Eigen rounding order
    recur_kernel<<<128, 256>>>(inputs, hidden, emb, Wx0, Wh0, bh0, Wy0, by0,
                               Wx1, Wh1, bh1, out);
    // 3) one big logits GEMM: (S*B, H) x (V, H)^T -> (S*B, V)
    gemm_logits_kernel<<<dim3(79, 32), 256>>>(Wy1, by1, out);
}

// round 7
// speedup vs baseline: 1.7070x; 1.7070x over previous
#include <cuda_runtime.h>
#include <cuda_bf16.h>

#define S_ 64
#define B_ 64
#define V_ 10000
#define E_ 256
#define H_ 512

// ---------------- device scratch (static: no allocations allowed) ----------------
__device__ float g_h0[B_ * H_];          // current-step layer-0 hidden
__device__ float g_y0[B_ * H_];          // current-step layer-0 output (y0 = Wy0 h0 + by0)
__device__ float g_h1all[S_ * B_ * H_];  // all layer-1 hiddens (feeds logits GEMM)
__device__ unsigned g_bar_cnt;
__device__ volatile unsigned g_bar_gen;

// ---------------- XLA/Eigen fast-tanh clone (bit-emulation of the reference) --------
// DO NOT TOUCH: trajectory is bit-exact vs XLA:CPU; any change re-injects error that
// the recurrence amplifies ~2e4x.
__device__ __forceinline__ float tanh_xla(float x)
{
    if (fabsf(x) < 0.0004f) return x;            // XLA tiny-x shortcut
    float xc = fminf(fmaxf(x, -9.0f), 9.0f);     // clamp
    float x2 = xc * xc;
    float a = -2.76076847742355e-16f;            // alpha_13
    a = __fmaf_rn(a, x2, 2.00018790482477e-13f); // alpha_11
    a = __fmaf_rn(a, x2, -8.60467152213735e-11f);// alpha_9
    a = __fmaf_rn(a, x2, 5.12229709037114e-08f); // alpha_7
    a = __fmaf_rn(a, x2, 1.48572235717979e-05f); // alpha_5
    a = __fmaf_rn(a, x2, 6.37261928875436e-04f); // alpha_3
    a = __fmaf_rn(a, x2, 4.89352455891786e-03f); // alpha_1
    float num = xc * a;
    float q = 1.19825839466702e-06f;             // beta_6
    q = __fmaf_rn(q, x2, 1.18534705686654e-04f); // beta_4
    q = __fmaf_rn(q, x2, 2.26843463243900e-03f); // beta_2
    q = __fmaf_rn(q, x2, 4.89352518554385e-03f); // beta_0
    return __fdiv_rn(num, q);                    // IEEE divide
}

// ---------------- fast grid barrier: atomic arrival + volatile-load spin -----------
// The old version spun with atomicAdd(&gen,0): 127 CTAs hammering one L2 atomic
// serializes (~0.85cyc/lane) -> tens of us per barrier x 192 barriers. Reads don't
// serialize: waiters poll a volatile load; only arrival is atomic.
__device__ __forceinline__ void grid_bar(unsigned epoch)
{
    __syncthreads();
    if (threadIdx.x == 0) {
        __threadfence();
        unsigned prev = atomicAdd(&g_bar_cnt, 1u);
        if (prev == gridDim.x - 1u) {
            atomicExch(&g_bar_cnt, 0u);   // reset BEFORE publishing epoch
            __threadfence();
            g_bar_gen = epoch;            // publish (volatile store)
        } else {
            while (g_bar_gen < epoch) { } // volatile poll: L2 read, no serialization
            __threadfence();
        }
    }
    __syncthreads();
}

__global__ void init_bar_kernel()
{
    g_bar_cnt = 0u;
    g_bar_gen = 0u;
}

// ---------------- recurrence: persistent kernel, 128 CTAs x 256 threads ----------------
// CTA bx owns output columns [bx*4, bx*4+4); thread = (b in 0..63) x (cj in 0..3).
// seg_dot: EXACT Eigen-order dot: single fp32 accumulator from 0, k strictly
// ascending, one __fmaf_rn per term. Chunked 128-wide through smem; float4 reads,
// the 4 fmas inside a float4 remain in ascending-k order.
#define CHUNK 128
#define XPAD  132   // 132*4B row stride: float4-aligned; 4-phase LDS.128 (structural floor)

__device__ __forceinline__ float seg_dot(
    float acc, const float* x, const float* emb_g, const float* __restrict__ wmat,
    int len, int colbase, float (*Xs)[XPAD], float (*Ws)[CHUNK], const int* sb,
    int b, int cj)
{
    int tid = threadIdx.x;
    int r = tid >> 2;          // row this thread stages (0..63)
    int q = tid & 3;           // quarter of the row (32 floats each)
    for (int kk = 0; kk < len; kk += CHUNK) {
        __syncthreads();
        {   // stage X tile: 64 rows x 128 cols, 8 float4 per thread
            const float* src = x ? (x + (size_t)r * H_ + kk)
                                 : (emb_g + (size_t)sb[r] + kk);
#pragma unroll
            for (int i = 0; i < 8; i++) {
                int c = q * 32 + i * 4;
                float4 v = *(const float4*)(src + c);
                *(float4*)&Xs[r][c] = v;
            }
        }
        if (tid < 128) {  // stage W tile: 4 cols x 128, 1 float4 per thread
            int c = tid >> 5, j = (tid & 31) * 4;
            float4 v = *(const float4*)(wmat + (size_t)(colbase + c) * len + kk + j);
            *(float4*)&Ws[c][j] = v;
        }
        __syncthreads();
        const float4* xv4 = (const float4*)&Xs[b][0];
        const float4* wv4 = (const float4*)&Ws[cj][0];
#pragma unroll
        for (int k4 = 0; k4 < CHUNK / 4; k4++) {
            float4 xv = xv4[k4];
            float4 wv = wv4[k4];   // warp-broadcast (same cj across warp)
            acc = __fmaf_rn(xv.x, wv.x, acc);
            acc = __fmaf_rn(xv.y, wv.y, acc);
            acc = __fmaf_rn(xv.z, wv.z, acc);
            acc = __fmaf_rn(xv.w, wv.w, acc);
        }
    }
    return acc;
}

__global__ __launch_bounds__(256) void recur_kernel(
    const int* __restrict__ inputs, const float* __restrict__ hidden,
    const float* __restrict__ emb,
    const float* __restrict__ Wx0, const float* __restrict__ Wh0,
    const float* __restrict__ bh0,
    const float* __restrict__ Wy0, const float* __restrict__ by0,
    const float* __restrict__ Wx1, const float* __restrict__ Wh1,
    const float* __restrict__ bh1,
    float* __restrict__ out)
{
    __shared__ float Xs[64][XPAD];
    __shared__ float Ws[4][CHUNK];
    __shared__ int sb[64];
    int tid = threadIdx.x;
    int b = tid & 63;
    int cj = tid >> 6;
    int colbase = blockIdx.x * 4;
    int col = colbase + cj;
    float* out_states = out + (size_t)S_ * B_ * V_;
    unsigned epoch = 0;

    for (int t = 0; t < S_; t++) {
        if (tid < 64) sb[tid] = inputs[t * B_ + tid] * E_;

        // ---- phase 1: h0 = tanh((emb_t@Wx0^T + p0@Wh0^T) + bh0)
        float d1 = seg_dot(0.f, nullptr, emb, Wx0, E_, colbase, Xs, Ws, sb, b, cj);
        const float* P0 = (t == 0) ? hidden : (g_h1all + (size_t)(t - 1) * B_ * H_);
        float d2 = seg_dot(0.f, P0, nullptr, Wh0, H_, colbase, Xs, Ws, sb, b, cj);
        float h0v = tanh_xla((d1 + d2) + bh0[col]);
        g_h0[(size_t)b * H_ + col] = h0v;
        if (t == S_ - 1) out_states[(size_t)b * H_ + col] = h0v;
        grid_bar(++epoch);

        // ---- phase 2: y0 = h0@Wy0^T + by0
        float dy = seg_dot(0.f, g_h0, nullptr, Wy0, H_, colbase, Xs, Ws, sb, b, cj);
        g_y0[(size_t)b * H_ + col] = dy + by0[col];
        grid_bar(++epoch);

        // ---- phase 3: h1 = tanh((y0@Wx1^T + p1@Wh1^T) + bh1)
        float e1 = seg_dot(0.f, g_y0, nullptr, Wx1, H_, colbase, Xs, Ws, sb, b, cj);
        const float* P1 = (t == 0) ? (hidden + (size_t)B_ * H_) : g_h0;
        float e2 = seg_dot(0.f, P1, nullptr, Wh1, H_, colbase, Xs, Ws, sb, b, cj);
        float h1v = tanh_xla((e1 + e2) + bh1[col]);
        g_h1all[(size_t)t * B_ * H_ + (size_t)b * H_ + col] = h1v;
        if (t == S_ - 1) out_states[(size_t)B_ * H_ + (size_t)b * H_ + col] = h1v;
        grid_bar(++epoch);
    }
}

// ---------------- logits: C[4096,10000] = H1all[4096,512] @ Wy1[10000,512]^T + by1 ----
// Per-element: single fp32 accumulator, k ascending, one fma per term, bias last
// -> same rounding sequence as the reference. (Terminal op: error non-amplified,
// but we keep it exact; it's already near the fp32 FFMA roofline.)
__global__ __launch_bounds__(256) void gemm_logits_kernel(
    const float* __restrict__ Bw, const float* __restrict__ bias,
    float* __restrict__ C)
{
    const int Kd = H_;
    const int N  = V_;
    const float* A = g_h1all;
    __shared__ float As[16][132];
    __shared__ float Bs[16][132];
    int tid = threadIdx.x;
    int m0 = blockIdx.y * 128;
    int n0 = blockIdx.x * 128;
    int tm = tid >> 4;
    int tn = tid & 15;
    float acc[8][8];
#pragma unroll
    for (int i = 0; i < 8; i++)
#pragma unroll
        for (int j = 0; j < 8; j++) acc[i][j] = 0.f;

    for (int kk = 0; kk < Kd; kk += 16) {
#pragma unroll
        for (int i = 0; i < 2; i++) {
            int fi = tid + i * 256;
            int row = fi >> 2, seg = fi & 3;
            float4 v = *(const float4*)(A + (size_t)(m0 + row) * Kd + kk + seg * 4);
            As[seg * 4 + 0][row] = v.x; As[seg * 4 + 1][row] = v.y;
            As[seg * 4 + 2][row] = v.z; As[seg * 4 + 3][row] = v.w;
        }
#pragma unroll
        for (int i = 0; i < 2; i++) {
            int fi = tid + i * 256;
            int row = fi >> 2, seg = fi & 3;
            int n = n0 + row;
            float4 v = make_float4(0.f, 0.f, 0.f, 0.f);
            if (n < N) v = *(const float4*)(Bw + (size_t)n * Kd + kk + seg * 4);
            Bs[seg * 4 + 0][row] = v.x; Bs[seg * 4 + 1][row] = v.y;
            Bs[seg * 4 + 2][row] = v.z; Bs[seg * 4 + 3][row] = v.w;
        }
        __syncthreads();
#pragma unroll
        for (int k = 0; k < 16; k++) {   // k strictly ascending; one fma per element
            float4 a0 = *(const float4*)&As[k][tm * 4];
            float4 a1 = *(const float4*)&As[k][tm * 4 + 64];
            float4 b0 = *(const float4*)&Bs[k][tn * 4];
            float4 b1 = *(const float4*)&Bs[k][tn * 4 + 64];
            float av[8] = {a0.x, a0.y, a0.z, a0.w, a1.x, a1.y, a1.z, a1.w};
            float bv[8] = {b0.x, b0.y, b0.z, b0.w, b1.x, b1.y, b1.z, b1.w};
#pragma unroll
            for (int i = 0; i < 8; i++)
#pragma unroll
                for (int j = 0; j < 8; j++)
                    acc[i][j] = __fmaf_rn(av[i], bv[j], acc[i][j]);
        }
        __syncthreads();
    }

#pragma unroll
    for (int i = 0; i < 8; i++) {
        int m = m0 + ((i < 4) ? (tm * 4 + i) : (64 + tm * 4 + i - 4));
#pragma unroll
        for (int jq = 0; jq < 2; jq++) {
            int c0 = n0 + tn * 4 + jq * 64;
            if (c0 < N) {
                float4 o;
                o.x = acc[i][jq * 4 + 0] + bias[c0 + 0];
                o.y = acc[i][jq * 4 + 1] + bias[c0 + 1];
                o.z = acc[i][jq * 4 + 2] + bias[c0 + 2];
                o.w = acc[i][jq * 4 + 3] + bias[c0 + 3];
                *(float4*)(C + (size_t)m * N + c0) = o;
            }
        }
    }
}

// ---------------- launch ----------------
extern "C" void kernel_launch(void* const* d_in, const int* in_sizes, int n_in,
                              void* d_out, int out_size)
{
    const int*   inputs = (const int*)d_in[0];
    const float* hidden = (const float*)d_in[1];
    const float* emb    = (const float*)d_in[2];
    const float* Wx0    = (const float*)d_in[3];
    const float* Wh0    = (const float*)d_in[4];
    const float* bh0    = (const float*)d_in[5];
    const float* Wy0    = (const float*)d_in[6];
    const float* by0    = (const float*)d_in[7];
    const float* Wx1    = (const float*)d_in[8];
    const float* Wh1    = (const float*)d_in[9];
    const float* bh1    = (const float*)d_in[10];
    const float* Wy1    = (const float*)d_in[11];
    const float* by1    = (const float*)d_in[12];
    float* out = (float*)d_out;

    (void)in_sizes; (void)n_in; (void)out_size;

    // 1) reset grid barrier (required for every graph replay)
    init_bar_kernel<<<1, 1>>>();
    // 2) sequential recurrence, bit-emulating XLA:CPU/Eigen rounding order
    recur_kernel<<<128, 256>>>(inputs, hidden, emb, Wx0, Wh0, bh0, Wy0, by0,
                               Wx1, Wh1, bh1, out);
    // 3) one big logits GEMM: (S*B, H) x (V, H)^T -> (S*B, V)
    gemm_logits_kernel<<<dim3(79, 32), 256>>>(Wy1, by1, out);
}

// round 8
// speedup vs baseline: 2.7844x; 1.6311x over previous
#include <cuda_runtime.h>
#include <cuda_bf16.h>

#define S_ 64
#define B_ 64
#define V_ 10000
#define E_ 256
#define H_ 512

// ---------------- device scratch (static: no allocations allowed) ----------------
__device__ float g_h0[B_ * H_];          // current-step layer-0 hidden
__device__ float g_y0[B_ * H_];          // current-step layer-0 output
__device__ float g_h1all[S_ * B_ * H_];  // all layer-1 hiddens (feeds logits GEMM)
__device__ unsigned g_bar_cnt;
__device__ volatile unsigned g_bar_gen;

// ---------------- XLA/Eigen fast-tanh clone (bit-emulation of the reference) --------
// DO NOT TOUCH: trajectory is bit-exact vs XLA:CPU; any change re-injects error that
// the recurrence amplifies ~2e4x.
__device__ __forceinline__ float tanh_xla(float x)
{
    if (fabsf(x) < 0.0004f) return x;            // XLA tiny-x shortcut
    float xc = fminf(fmaxf(x, -9.0f), 9.0f);     // clamp
    float x2 = xc * xc;
    float a = -2.76076847742355e-16f;            // alpha_13
    a = __fmaf_rn(a, x2, 2.00018790482477e-13f); // alpha_11
    a = __fmaf_rn(a, x2, -8.60467152213735e-11f);// alpha_9
    a = __fmaf_rn(a, x2, 5.12229709037114e-08f); // alpha_7
    a = __fmaf_rn(a, x2, 1.48572235717979e-05f); // alpha_5
    a = __fmaf_rn(a, x2, 6.37261928875436e-04f); // alpha_3
    a = __fmaf_rn(a, x2, 4.89352455891786e-03f); // alpha_1
    float num = xc * a;
    float q = 1.19825839466702e-06f;             // beta_6
    q = __fmaf_rn(q, x2, 1.18534705686654e-04f); // beta_4
    q = __fmaf_rn(q, x2, 2.26843463243900e-03f); // beta_2
    q = __fmaf_rn(q, x2, 4.89352518554385e-03f); // beta_0
    return __fdiv_rn(num, q);                    // IEEE divide
}

// ---------------- grid barrier (proven in round 7) ---------------------------------
__device__ __forceinline__ void grid_bar(unsigned epoch)
{
    __syncthreads();
    if (threadIdx.x == 0) {
        __threadfence();
        unsigned prev = atomicAdd(&g_bar_cnt, 1u);
        if (prev == gridDim.x - 1u) {
            atomicExch(&g_bar_cnt, 0u);   // reset BEFORE publishing epoch
            __threadfence();
            g_bar_gen = epoch;            // publish (volatile store)
        } else {
            while (g_bar_gen < epoch) { } // volatile poll
            __threadfence();
        }
    }
    __syncthreads();
}

__global__ void init_bar_kernel()
{
    g_bar_cnt = 0u;
    g_bar_gen = 0u;
}

// ---------------- cp.async helpers -------------------------------------------------
#define CPA16(dst, src) asm volatile("cp.async.cg.shared.global [%0], [%1], 16;" :: "r"(dst), "l"(src) : "memory")
#define CPC()  asm volatile("cp.async.commit_group;" ::: "memory")
#define CPW1() asm volatile("cp.async.wait_group 1;" ::: "memory")
#define CPW0() asm volatile("cp.async.wait_group 0;" ::: "memory")

__device__ __forceinline__ unsigned smem_u32(const void* p)
{
    return (unsigned)__cvta_generic_to_shared(p);
}

// ---------------- dynamic smem layout (floats) -------------------------------------
// XA[2][64][132]  @ 0       (8448 per buf)   X tile A, double buffered
// XB[2][64][132]  @ 16896                    X tile B, double buffered
// WA[2][4][128]   @ 33792   (512 per buf)    W tile A
// WB[2][4][128]   @ 34816                    W tile B
// sb[64] (int)    @ 35840
// total 35904 floats = 143616 bytes
#define SMEM_DYN_BYTES 143616
#define XA(i) (sm + (i) * 8448)
#define XB(i) (sm + 16896 + (i) * 8448)
#define WA(i) (sm + 33792 + (i) * 512)
#define WB(i) (sm + 34816 + (i) * 512)

// stage one 64x128 X chunk, COALESCED: warp = one contiguous 512B row-chunk (4 wf)
__device__ __forceinline__ void stage_x(float* Xs, const float* base, int ck)
{
    int row = threadIdx.x >> 5, lane = threadIdx.x & 31;
#pragma unroll
    for (int i = 0; i < 8; i++) {
        int r = row + i * 8;
        unsigned dst = smem_u32(Xs + r * 132 + lane * 4);
        CPA16(dst, base + (size_t)r * H_ + ck * 128 + lane * 4);
    }
}

// gather-staged emb rows (per-row base from sb)
__device__ __forceinline__ void stage_emb(float* Xs, const float* emb, const int* sbp, int ck)
{
    int row = threadIdx.x >> 5, lane = threadIdx.x & 31;
#pragma unroll
    for (int i = 0; i < 8; i++) {
        int r = row + i * 8;
        unsigned dst = smem_u32(Xs + r * 132 + lane * 4);
        CPA16(dst, emb + (size_t)sbp[r] + ck * 128 + lane * 4);
    }
}

// stage 4x128 W chunk (rows colbase..colbase+3), coalesced
__device__ __forceinline__ void stage_w(float* Ws, const float* W, int len, int colbase, int ck)
{
    if (threadIdx.x < 128) {
        int row = threadIdx.x >> 5, lane = threadIdx.x & 31;
        unsigned dst = smem_u32(Ws + row * 128 + lane * 4);
        CPA16(dst, W + (size_t)(colbase + row) * len + ck * 128 + lane * 4);
    }
}

// EXACT Eigen-order chunk: single accumulator, k strictly ascending, one fma/term
__device__ __forceinline__ float comp1(float acc, const float* Xs, const float* Ws,
                                       int b, int cj)
{
    const float4* xv = (const float4*)(Xs + b * 132);
    const float4* wv = (const float4*)(Ws + cj * 128);
#pragma unroll
    for (int k = 0; k < 32; k++) {
        float4 x = xv[k];
        float4 w = wv[k];
        acc = __fmaf_rn(x.x, w.x, acc);
        acc = __fmaf_rn(x.y, w.y, acc);
        acc = __fmaf_rn(x.z, w.z, acc);
        acc = __fmaf_rn(x.w, w.w, acc);
    }
    return acc;
}

// ---------------- recurrence: persistent, 128 CTAs x 256 threads --------------------
// CTA owns cols [bx*4, bx*4+4); thread = (b, cj). Slots per step:
//   A: d2 = P0@Wh0      -> h0 = tanh((d1+d2)+bh0)            [d1 prefetched last step]
//   B: dy = h0@Wy0, e2 = P1@Wh1  -> y0 = dy+by0
//   C: e1 = y0@Wx1, d1n = emb[t+1]@Wx0 -> h1 = tanh((e1+e2)+bh1)
__global__ __launch_bounds__(256, 1) void recur_kernel(
    const int* __restrict__ inputs, const float* __restrict__ hidden,
    const float* __restrict__ emb,
    const float* __restrict__ Wx0, const float* __restrict__ Wh0,
    const float* __restrict__ bh0,
    const float* __restrict__ Wy0, const float* __restrict__ by0,
    const float* __restrict__ Wx1, const float* __restrict__ Wh1,
    const float* __restrict__ bh1,
    float* __restrict__ out)
{
    extern __shared__ float sm[];
    int* sbp = (int*)(sm + 35840);
    int tid = threadIdx.x;
    int b = tid & 63;
    int cj = tid >> 6;
    int colbase = blockIdx.x * 4;
    int col = colbase + cj;
    float* out_states = out + (size_t)S_ * B_ * V_;
    unsigned epoch = 0;

    // ---- prologue: sb for t=0, then d1(0) = emb[0]@Wx0 (2 chunks, pipelined)
    if (tid < 64) sbp[tid] = inputs[tid] * E_;
    __syncthreads();
    float d1 = 0.f;
    {
        stage_emb(XB(0), emb, sbp, 0);
        stage_w(WB(0), Wx0, E_, colbase, 0);
        CPC();
#pragma unroll
        for (int ck = 0; ck < 2; ck++) {
            if (ck < 1) {
                stage_emb(XB(1), emb, sbp, 1);
                stage_w(WB(1), Wx0, E_, colbase, 1);
                CPC(); CPW1();
            } else CPW0();
            __syncthreads();
            d1 = comp1(d1, XB(ck), WB(ck), b, cj);
            __syncthreads();
        }
    }

    for (int t = 0; t < S_; t++) {
        // ================= slot A: d2 = P0 @ Wh0 =================
        const float* P0 = (t == 0) ? hidden : (g_h1all + (size_t)(t - 1) * B_ * H_);
        float d2 = 0.f;
        stage_x(XA(0), P0, 0);
        stage_w(WA(0), Wh0, H_, colbase, 0);
        CPC();
#pragma unroll
        for (int ck = 0; ck < 4; ck++) {
            int cb = ck & 1, nb = (ck + 1) & 1;
            if (ck < 3) {
                stage_x(XA(nb), P0, ck + 1);
                stage_w(WA(nb), Wh0, H_, colbase, ck + 1);
                CPC(); CPW1();
            } else CPW0();
            __syncthreads();
            d2 = comp1(d2, XA(cb), WA(cb), b, cj);
            __syncthreads();
        }
        float h0v = tanh_xla((d1 + d2) + bh0[col]);
        g_h0[(size_t)b * H_ + col] = h0v;
        if (t == S_ - 1) out_states[(size_t)b * H_ + col] = h0v;
        grid_bar(++epoch);

        // ================= slot B: dy = h0@Wy0, e2 = P1@Wh1 =================
        const float* P1 = (t == 0) ? (hidden + (size_t)B_ * H_) : g_h0;
        float dy = 0.f, e2 = 0.f;
        stage_x(XA(0), g_h0, 0);
        stage_x(XB(0), P1, 0);
        stage_w(WA(0), Wy0, H_, colbase, 0);
        stage_w(WB(0), Wh1, H_, colbase, 0);
        CPC();
#pragma unroll
        for (int ck = 0; ck < 4; ck++) {
            int cb = ck & 1, nb = (ck + 1) & 1;
            if (ck < 3) {
                stage_x(XA(nb), g_h0, ck + 1);
                stage_x(XB(nb), P1, ck + 1);
                stage_w(WA(nb), Wy0, H_, colbase, ck + 1);
                stage_w(WB(nb), Wh1, H_, colbase, ck + 1);
                CPC(); CPW1();
            } else CPW0();
            __syncthreads();
            dy = comp1(dy, XA(cb), WA(cb), b, cj);   // independent chains ->
            e2 = comp1(e2, XB(cb), WB(cb), b, cj);   // ptxas interleaves (ILP=2)
            __syncthreads();
        }
        g_y0[(size_t)b * H_ + col] = dy + by0[col];
        if (t < S_ - 1 && tid < 64) sbp[tid] = inputs[(t + 1) * B_ + tid] * E_;
        grid_bar(++epoch);   // barrier syncthreads also publishes sbp CTA-locally

        // ================= slot C: e1 = y0@Wx1 (+ prefetch d1(t+1)) =================
        bool doemb = (t < S_ - 1);
        float e1 = 0.f, d1n = 0.f;
        stage_x(XA(0), g_y0, 0);
        stage_w(WA(0), Wx1, H_, colbase, 0);
        if (doemb) {
            stage_emb(XB(0), emb, sbp, 0);
            stage_w(WB(0), Wx0, E_, colbase, 0);
        }
        CPC();
#pragma unroll
        for (int ck = 0; ck < 4; ck++) {
            int cb = ck & 1, nb = (ck + 1) & 1;
            if (ck < 3) {
                stage_x(XA(nb), g_y0, ck + 1);
                stage_w(WA(nb), Wx1, H_, colbase, ck + 1);
                if (doemb && ck + 1 < 2) {
                    stage_emb(XB(nb), emb, sbp, ck + 1);
                    stage_w(WB(nb), Wx0, E_, colbase, ck + 1);
                }
                CPC(); CPW1();
            } else CPW0();
            __syncthreads();
            e1 = comp1(e1, XA(cb), WA(cb), b, cj);
            if (doemb && ck < 2) d1n = comp1(d1n, XB(cb), WB(cb), b, cj);
            __syncthreads();
        }
        float h1v = tanh_xla((e1 + e2) + bh1[col]);
        g_h1all[(size_t)t * B_ * H_ + (size_t)b * H_ + col] = h1v;
        if (t == S_ - 1) out_states[(size_t)B_ * H_ + (size_t)b * H_ + col] = h1v;
        grid_bar(++epoch);
        d1 = d1n;   // carry prefetched first-dot into next step
    }
}

// ---------------- logits: C[4096,10000] = H1all[4096,512] @ Wy1[10000,512]^T + by1 ----
// Per-element: single fp32 accumulator, k ascending, one fma per term, bias last.
__global__ __launch_bounds__(256) void gemm_logits_kernel(
    const float* __restrict__ Bw, const float* __restrict__ bias,
    float* __restrict__ C)
{
    const int Kd = H_;
    const int N  = V_;
    const float* A = g_h1all;
    __shared__ float As[16][132];
    __shared__ float Bs[16][132];
    int tid = threadIdx.x;
    int m0 = blockIdx.y * 128;
    int n0 = blockIdx.x * 128;
    int tm = tid >> 4;
    int tn = tid & 15;
    float acc[8][8];
#pragma unroll
    for (int i = 0; i < 8; i++)
#pragma unroll
        for (int j = 0; j < 8; j++) acc[i][j] = 0.f;

    for (int kk = 0; kk < Kd; kk += 16) {
#pragma unroll
        for (int i = 0; i < 2; i++) {
            int fi = tid + i * 256;
            int row = fi >> 2, seg = fi & 3;
            float4 v = *(const float4*)(A + (size_t)(m0 + row) * Kd + kk + seg * 4);
            As[seg * 4 + 0][row] = v.x; As[seg * 4 + 1][row] = v.y;
            As[seg * 4 + 2][row] = v.z; As[seg * 4 + 3][row] = v.w;
        }
#pragma unroll
        for (int i = 0; i < 2; i++) {
            int fi = tid + i * 256;
            int row = fi >> 2, seg = fi & 3;
            int n = n0 + row;
            float4 v = make_float4(0.f, 0.f, 0.f, 0.f);
            if (n < N) v = *(const float4*)(Bw + (size_t)n * Kd + kk + seg * 4);
            Bs[seg * 4 + 0][row] = v.x; Bs[seg * 4 + 1][row] = v.y;
            Bs[seg * 4 + 2][row] = v.z; Bs[seg * 4 + 3][row] = v.w;
        }
        __syncthreads();
#pragma unroll
        for (int k = 0; k < 16; k++) {
            float4 a0 = *(const float4*)&As[k][tm * 4];
            float4 a1 = *(const float4*)&As[k][tm * 4 + 64];
            float4 b0 = *(const float4*)&Bs[k][tn * 4];
            float4 b1 = *(const float4*)&Bs[k][tn * 4 + 64];
            float av[8] = {a0.x, a0.y, a0.z, a0.w, a1.x, a1.y, a1.z, a1.w};
            float bv[8] = {b0.x, b0.y, b0.z, b0.w, b1.x, b1.y, b1.z, b1.w};
#pragma unroll
            for (int i = 0; i < 8; i++)
#pragma unroll
                for (int j = 0; j < 8; j++)
                    acc[i][j] = __fmaf_rn(av[i], bv[j], acc[i][j]);
        }
        __syncthreads();
    }

#pragma unroll
    for (int i = 0; i < 8; i++) {
        int m = m0 + ((i < 4) ? (tm * 4 + i) : (64 + tm * 4 + i - 4));
#pragma unroll
        for (int jq = 0; jq < 2; jq++) {
            int c0 = n0 + tn * 4 + jq * 64;
            if (c0 < N) {
                float4 o;
                o.x = acc[i][jq * 4 + 0] + bias[c0 + 0];
                o.y = acc[i][jq * 4 + 1] + bias[c0 + 1];
                o.z = acc[i][jq * 4 + 2] + bias[c0 + 2];
                o.w = acc[i][jq * 4 + 3] + bias[c0 + 3];
                *(float4*)(C + (size_t)m * N + c0) = o;
            }
        }
    }
}

// ---------------- launch ----------------
extern "C" void kernel_launch(void* const* d_in, const int* in_sizes, int n_in,
                              void* d_out, int out_size)
{
    const int*   inputs = (const int*)d_in[0];
    const float* hidden = (const float*)d_in[1];
    const float* emb    = (const float*)d_in[2];
    const float* Wx0    = (const float*)d_in[3];
    const float* Wh0    = (const float*)d_in[4];
    const float* bh0    = (const float*)d_in[5];
    const float* Wy0    = (const float*)d_in[6];
    const float* by0    = (const float*)d_in[7];
    const float* Wx1    = (const float*)d_in[8];
    const float* Wh1    = (const float*)d_in[9];
    const float* bh1    = (const float*)d_in[10];
    const float* Wy1    = (const float*)d_in[11];
    const float* by1    = (const float*)d_in[12];
    float* out = (float*)d_out;

    (void)in_sizes; (void)n_in; (void)out_size;

    // raise dynamic smem cap for the recurrence kernel (idempotent; first call is
    // outside graph capture, so the attribute is set before any captured launch)
    static int attr_done = 0;
    if (!attr_done) {
        cudaFuncSetAttribute(recur_kernel,
                             cudaFuncAttributeMaxDynamicSharedMemorySize,
                             SMEM_DYN_BYTES);
        attr_done = 1;
    }

    // 1) reset grid barrier (required for every graph replay)
    init_bar_kernel<<<1, 1>>>();
    // 2) sequential recurrence, bit-emulating XLA:CPU/Eigen rounding order
    recur_kernel<<<128, 256, SMEM_DYN_BYTES>>>(inputs, hidden, emb,
                                               Wx0, Wh0, bh0, Wy0, by0,
                                               Wx1, Wh1, bh1, out);
    // 3) one big logits GEMM: (S*B, H) x (V, H)^T -> (S*B, V)
    gemm_logits_kernel<<<dim3(79, 32), 256>>>(Wy1, by1, out);
}

// round 10
// speedup vs baseline: 3.2149x; 1.1546x over previous
#include <cuda_runtime.h>
#include <cuda_bf16.h>
#include <cstdint>

#define S_ 64
#define B_ 64
#define V_ 10000
#define E_ 256
#define H_ 512

#define KSPLIT 1536           // K' = 3*H : [hi|hi|lo] x [hi|lo|hi]
#define NPAD   10112          // 79 tiles of 128

// ---------------- device scratch (static: no allocations allowed) ----------------
__device__ float g_h0[B_ * H_];
__device__ float g_y0[B_ * H_];
__device__ float g_h1all[S_ * B_ * H_];
__device__ unsigned g_bar_cnt;
__device__ volatile unsigned g_bar_gen;

// bf16 split operands for the logits GEMM (A'' 12.6MB, B'' 31.1MB)
__device__ __nv_bfloat16 g_A2[(size_t)S_ * B_ * KSPLIT];
__device__ __nv_bfloat16 g_B2[(size_t)NPAD * KSPLIT];

// ---------------- XLA/Eigen fast-tanh clone (bit-exact vs reference) ----------------
// DO NOT TOUCH: recurrence trajectory is bit-exact vs XLA:CPU (amplifies ~2e4x).
__device__ __forceinline__ float tanh_xla(float x)
{
    if (fabsf(x) < 0.0004f) return x;
    float xc = fminf(fmaxf(x, -9.0f), 9.0f);
    float x2 = xc * xc;
    float a = -2.76076847742355e-16f;
    a = __fmaf_rn(a, x2, 2.00018790482477e-13f);
    a = __fmaf_rn(a, x2, -8.60467152213735e-11f);
    a = __fmaf_rn(a, x2, 5.12229709037114e-08f);
    a = __fmaf_rn(a, x2, 1.48572235717979e-05f);
    a = __fmaf_rn(a, x2, 6.37261928875436e-04f);
    a = __fmaf_rn(a, x2, 4.89352455891786e-03f);
    float num = xc * a;
    float q = 1.19825839466702e-06f;
    q = __fmaf_rn(q, x2, 1.18534705686654e-04f);
    q = __fmaf_rn(q, x2, 2.26843463243900e-03f);
    q = __fmaf_rn(q, x2, 4.89352518554385e-03f);
    return __fdiv_rn(num, q);
}

// ---------------- grid barrier (proven) --------------------------------------------
__device__ __forceinline__ void grid_bar(unsigned epoch)
{
    __syncthreads();
    if (threadIdx.x == 0) {
        __threadfence();
        unsigned prev = atomicAdd(&g_bar_cnt, 1u);
        if (prev == gridDim.x - 1u) {
            atomicExch(&g_bar_cnt, 0u);
            __threadfence();
            g_bar_gen = epoch;
        } else {
            while (g_bar_gen < epoch) { }
            __threadfence();
        }
    }
    __syncthreads();
}

__global__ void init_bar_kernel()
{
    g_bar_cnt = 0u;
    g_bar_gen = 0u;
}

// ---------------- cp.async helpers -------------------------------------------------
#define CPA16(dst, src) asm volatile("cp.async.cg.shared.global [%0], [%1], 16;" :: "r"(dst), "l"(src) : "memory")
#define CPC()  asm volatile("cp.async.commit_group;" ::: "memory")
#define CPW1() asm volatile("cp.async.wait_group 1;" ::: "memory")
#define CPW0() asm volatile("cp.async.wait_group 0;" ::: "memory")

__device__ __forceinline__ unsigned smem_u32(const void* p)
{
    return (unsigned)__cvta_generic_to_shared(p);
}

// ---------------- recurrence machinery (unchanged from round 8, proven) -------------
#define SMEM_DYN_BYTES 143616
#define XA(i) (sm + (i) * 8448)
#define XB(i) (sm + 16896 + (i) * 8448)
#define WA(i) (sm + 33792 + (i) * 512)
#define WB(i) (sm + 34816 + (i) * 512)

__device__ __forceinline__ void stage_x(float* Xs, const float* base, int ck)
{
    int row = threadIdx.x >> 5, lane = threadIdx.x & 31;
#pragma unroll
    for (int i = 0; i < 8; i++) {
        int r = row + i * 8;
        unsigned dst = smem_u32(Xs + r * 132 + lane * 4);
        CPA16(dst, base + (size_t)r * H_ + ck * 128 + lane * 4);
    }
}

__device__ __forceinline__ void stage_emb(float* Xs, const float* emb, const int* sbp, int ck)
{
    int row = threadIdx.x >> 5, lane = threadIdx.x & 31;
#pragma unroll
    for (int i = 0; i < 8; i++) {
        int r = row + i * 8;
        unsigned dst = smem_u32(Xs + r * 132 + lane * 4);
        CPA16(dst, emb + (size_t)sbp[r] + ck * 128 + lane * 4);
    }
}

__device__ __forceinline__ void stage_w(float* Ws, const float* W, int len, int colbase, int ck)
{
    if (threadIdx.x < 128) {
        int row = threadIdx.x >> 5, lane = threadIdx.x & 31;
        unsigned dst = smem_u32(Ws + row * 128 + lane * 4);
        CPA16(dst, W + (size_t)(colbase + row) * len + ck * 128 + lane * 4);
    }
}

__device__ __forceinline__ float comp1(float acc, const float* Xs, const float* Ws,
                                       int b, int cj)
{
    const float4* xv = (const float4*)(Xs + b * 132);
    const float4* wv = (const float4*)(Ws + cj * 128);
#pragma unroll
    for (int k = 0; k < 32; k++) {
        float4 x = xv[k];
        float4 w = wv[k];
        acc = __fmaf_rn(x.x, w.x, acc);
        acc = __fmaf_rn(x.y, w.y, acc);
        acc = __fmaf_rn(x.z, w.z, acc);
        acc = __fmaf_rn(x.w, w.w, acc);
    }
    return acc;
}

__global__ __launch_bounds__(256, 1) void recur_kernel(
    const int* __restrict__ inputs, const float* __restrict__ hidden,
    const float* __restrict__ emb,
    const float* __restrict__ Wx0, const float* __restrict__ Wh0,
    const float* __restrict__ bh0,
    const float* __restrict__ Wy0, const float* __restrict__ by0,
    const float* __restrict__ Wx1, const float* __restrict__ Wh1,
    const float* __restrict__ bh1,
    float* __restrict__ out)
{
    extern __shared__ float sm[];
    int* sbp = (int*)(sm + 35840);
    int tid = threadIdx.x;
    int b = tid & 63;
    int cj = tid >> 6;
    int colbase = blockIdx.x * 4;
    int col = colbase + cj;
    float* out_states = out + (size_t)S_ * B_ * V_;
    unsigned epoch = 0;

    if (tid < 64) sbp[tid] = inputs[tid] * E_;
    __syncthreads();
    float d1 = 0.f;
    {
        stage_emb(XB(0), emb, sbp, 0);
        stage_w(WB(0), Wx0, E_, colbase, 0);
        CPC();
#pragma unroll
        for (int ck = 0; ck < 2; ck++) {
            if (ck < 1) {
                stage_emb(XB(1), emb, sbp, 1);
                stage_w(WB(1), Wx0, E_, colbase, 1);
                CPC(); CPW1();
            } else CPW0();
            __syncthreads();
            d1 = comp1(d1, XB(ck), WB(ck), b, cj);
            __syncthreads();
        }
    }

    for (int t = 0; t < S_; t++) {
        const float* P0 = (t == 0) ? hidden : (g_h1all + (size_t)(t - 1) * B_ * H_);
        float d2 = 0.f;
        stage_x(XA(0), P0, 0);
        stage_w(WA(0), Wh0, H_, colbase, 0);
        CPC();
#pragma unroll
        for (int ck = 0; ck < 4; ck++) {
            int cb = ck & 1, nb = (ck + 1) & 1;
            if (ck < 3) {
                stage_x(XA(nb), P0, ck + 1);
                stage_w(WA(nb), Wh0, H_, colbase, ck + 1);
                CPC(); CPW1();
            } else CPW0();
            __syncthreads();
            d2 = comp1(d2, XA(cb), WA(cb), b, cj);
            __syncthreads();
        }
        float h0v = tanh_xla((d1 + d2) + bh0[col]);
        g_h0[(size_t)b * H_ + col] = h0v;
        if (t == S_ - 1) out_states[(size_t)b * H_ + col] = h0v;
        grid_bar(++epoch);

        const float* P1 = (t == 0) ? (hidden + (size_t)B_ * H_) : g_h0;
        float dy = 0.f, e2 = 0.f;
        stage_x(XA(0), g_h0, 0);
        stage_x(XB(0), P1, 0);
        stage_w(WA(0), Wy0, H_, colbase, 0);
        stage_w(WB(0), Wh1, H_, colbase, 0);
        CPC();
#pragma unroll
        for (int ck = 0; ck < 4; ck++) {
            int cb = ck & 1, nb = (ck + 1) & 1;
            if (ck < 3) {
                stage_x(XA(nb), g_h0, ck + 1);
                stage_x(XB(nb), P1, ck + 1);
                stage_w(WA(nb), Wy0, H_, colbase, ck + 1);
                stage_w(WB(nb), Wh1, H_, colbase, ck + 1);
                CPC(); CPW1();
            } else CPW0();
            __syncthreads();
            dy = comp1(dy, XA(cb), WA(cb), b, cj);
            e2 = comp1(e2, XB(cb), WB(cb), b, cj);
            __syncthreads();
        }
        g_y0[(size_t)b * H_ + col] = dy + by0[col];
        if (t < S_ - 1 && tid < 64) sbp[tid] = inputs[(t + 1) * B_ + tid] * E_;
        grid_bar(++epoch);

        bool doemb = (t < S_ - 1);
        float e1 = 0.f, d1n = 0.f;
        stage_x(XA(0), g_y0, 0);
        stage_w(WA(0), Wx1, H_, colbase, 0);
        if (doemb) {
            stage_emb(XB(0), emb, sbp, 0);
            stage_w(WB(0), Wx0, E_, colbase, 0);
        }
        CPC();
#pragma unroll
        for (int ck = 0; ck < 4; ck++) {
            int cb = ck & 1, nb = (ck + 1) & 1;
            if (ck < 3) {
                stage_x(XA(nb), g_y0, ck + 1);
                stage_w(WA(nb), Wx1, H_, colbase, ck + 1);
                if (doemb && ck + 1 < 2) {
                    stage_emb(XB(nb), emb, sbp, ck + 1);
                    stage_w(WB(nb), Wx0, E_, colbase, ck + 1);
                }
                CPC(); CPW1();
            } else CPW0();
            __syncthreads();
            e1 = comp1(e1, XA(cb), WA(cb), b, cj);
            if (doemb && ck < 2) d1n = comp1(d1n, XB(cb), WB(cb), b, cj);
            __syncthreads();
        }
        float h1v = tanh_xla((e1 + e2) + bh1[col]);
        g_h1all[(size_t)t * B_ * H_ + (size_t)b * H_ + col] = h1v;
        if (t == S_ - 1) out_states[(size_t)B_ * H_ + (size_t)b * H_ + col] = h1v;
        grid_bar(++epoch);
        d1 = d1n;
    }
}

// ---------------- bf16 split pre-conversion -----------------------------------------
// x = hi + lo;  A'' row = [hi(512) | hi(512) | lo(512)],  B'' row = [hi | lo | hi].
// Sum over K'=1536 of A''*B'' = hi*hi + hi*lo + lo*hi  (drops only lo*lo ~2^-18).
__global__ __launch_bounds__(256) void preconvA_kernel()
{
    int row = blockIdx.x;          // 4096
    int t = threadIdx.x;           // 256 -> one float2 (2 cols) per thread
    float2 v = ((const float2*)(g_h1all + (size_t)row * H_))[t];
    __nv_bfloat16 h0 = __float2bfloat16(v.x);
    __nv_bfloat16 h1 = __float2bfloat16(v.y);
    __nv_bfloat16 l0 = __float2bfloat16(v.x - __bfloat162float(h0));
    __nv_bfloat16 l1 = __float2bfloat16(v.y - __bfloat162float(h1));
    __nv_bfloat162 hh; hh.x = h0; hh.y = h1;
    __nv_bfloat162 ll; ll.x = l0; ll.y = l1;
    __nv_bfloat162* dst = (__nv_bfloat162*)(g_A2 + (size_t)row * KSPLIT);
    dst[t] = hh; dst[256 + t] = hh; dst[512 + t] = ll;
}

__global__ __launch_bounds__(256) void preconvB_kernel(const float* __restrict__ Wy1)
{
    int row = blockIdx.x;          // NPAD
    int t = threadIdx.x;
    float2 v = make_float2(0.f, 0.f);
    if (row < V_) v = ((const float2*)(Wy1 + (size_t)row * H_))[t];
    __nv_bfloat16 h0 = __float2bfloat16(v.x);
    __nv_bfloat16 h1 = __float2bfloat16(v.y);
    __nv_bfloat16 l0 = __float2bfloat16(v.x - __bfloat162float(h0));
    __nv_bfloat16 l1 = __float2bfloat16(v.y - __bfloat162float(h1));
    __nv_bfloat162 hh; hh.x = h0; hh.y = h1;
    __nv_bfloat162 ll; ll.x = l0; ll.y = l1;
    __nv_bfloat162* dst = (__nv_bfloat162*)(g_B2 + (size_t)row * KSPLIT);
    dst[t] = hh; dst[256 + t] = ll; dst[512 + t] = hh;
}

// ---------------- logits GEMM on HMMA (mma.sync, base-ISA) --------------------------
// C[4096, 10000] = A''[4096, 1536] @ B''[NPAD, 1536]^T + bias.
// CTA 128x128, 8 warps (4x2), warp 32x64, K chunks of 32, cp.async double buffer.
// smem rows padded to 40 bf16 (80B = 5*16B: cp.async-aligned, conflict-free frags).
#define GSTR 40

__device__ __forceinline__ void mma16816(float* d, const unsigned* a, const unsigned* b)
{
    asm volatile(
        "mma.sync.aligned.m16n8k16.row.col.f32.bf16.bf16.f32 "
        "{%0,%1,%2,%3}, {%4,%5,%6,%7}, {%8,%9}, {%0,%1,%2,%3};"
        : "+f"(d[0]), "+f"(d[1]), "+f"(d[2]), "+f"(d[3])
        : "r"(a[0]), "r"(a[1]), "r"(a[2]), "r"(a[3]), "r"(b[0]), "r"(b[1]));
}

__global__ __launch_bounds__(256) void gemm_bf16_kernel(
    const float* __restrict__ bias, float* __restrict__ C)
{
    __shared__ __nv_bfloat16 Asm[2][128 * GSTR];
    __shared__ __nv_bfloat16 Bsm[2][128 * GSTR];
    int tid = threadIdx.x, lane = tid & 31, wid = tid >> 5;
    int wm = wid & 3, wn = wid >> 2;
    int m0 = blockIdx.y * 128, n0 = blockIdx.x * 128;
    const __nv_bfloat16* Ag = g_A2 + (size_t)m0 * KSPLIT;
    const __nv_bfloat16* Bg = g_B2 + (size_t)n0 * KSPLIT;

    float acc[2][8][4];
#pragma unroll
    for (int i = 0; i < 2; i++)
#pragma unroll
        for (int j = 0; j < 8; j++)
#pragma unroll
            for (int k = 0; k < 4; k++) acc[i][j][k] = 0.f;

    // stage chunk kc into buffer buf: A/B each 128 rows x 32 bf16 = 512 x 16B
#define STAGE(buf, kc)                                                          \
    {                                                                           \
        _Pragma("unroll")                                                       \
        for (int i = 0; i < 2; i++) {                                           \
            int e = tid + i * 256;                                              \
            int row = e >> 2, seg = e & 3;                                      \
            CPA16(smem_u32(&Asm[buf][row * GSTR + seg * 8]),                    \
                  Ag + (size_t)row * KSPLIT + (kc) * 32 + seg * 8);             \
            CPA16(smem_u32(&Bsm[buf][row * GSTR + seg * 8]),                    \
                  Bg + (size_t)row * KSPLIT + (kc) * 32 + seg * 8);             \
        }                                                                       \
    }

    STAGE(0, 0); CPC();

    int gr = lane >> 2, ck = (lane & 3) * 2;
    for (int kc = 0; kc < KSPLIT / 32; kc++) {
        int cur = kc & 1;
        if (kc < KSPLIT / 32 - 1) { STAGE(cur ^ 1, kc + 1); CPC(); CPW1(); }
        else CPW0();
        __syncthreads();
#pragma unroll
        for (int s = 0; s < 2; s++) {
            int kb = s * 16;
            unsigned afr[2][4], bfr[8][2];
#pragma unroll
            for (int mf = 0; mf < 2; mf++) {
                int r = wm * 32 + mf * 16 + gr;
                afr[mf][0] = *(const unsigned*)&Asm[cur][r * GSTR + kb + ck];
                afr[mf][1] = *(const unsigned*)&Asm[cur][(r + 8) * GSTR + kb + ck];
                afr[mf][2] = *(const unsigned*)&Asm[cur][r * GSTR + kb + ck + 8];
                afr[mf][3] = *(const unsigned*)&Asm[cur][(r + 8) * GSTR + kb + ck + 8];
            }
#pragma unroll
            for (int nf = 0; nf < 8; nf++) {
                int n = wn * 64 + nf * 8 + gr;
                bfr[nf][0] = *(const unsigned*)&Bsm[cur][n * GSTR + kb + ck];
                bfr[nf][1] = *(const unsigned*)&Bsm[cur][n * GSTR + kb + ck + 8];
            }
#pragma unroll
            for (int mf = 0; mf < 2; mf++)
#pragma unroll
                for (int nf = 0; nf < 8; nf++)
                    mma16816(acc[mf][nf], afr[mf], bfr[nf]);
        }
        __syncthreads();
    }

    // epilogue: bias add + store (rows gr / gr+8, cols (lane&3)*2 per frag)
    int cn = (lane & 3) * 2;
#pragma unroll
    for (int mf = 0; mf < 2; mf++) {
        int r = m0 + wm * 32 + mf * 16 + gr;
#pragma unroll
        for (int nf = 0; nf < 8; nf++) {
            int c = n0 + wn * 64 + nf * 8 + cn;
            if (c < V_) {
                float2 b2 = *(const float2*)(bias + c);
                float2 o0, o1;
                o0.x = acc[mf][nf][0] + b2.x;
                o0.y = acc[mf][nf][1] + b2.y;
                o1.x = acc[mf][nf][2] + b2.x;
                o1.y = acc[mf][nf][3] + b2.y;
                *(float2*)(C + (size_t)r * V_ + c) = o0;
                *(float2*)(C + (size_t)(r + 8) * V_ + c) = o1;
            }
        }
    }
}

// ---------------- launch ----------------
extern "C" void kernel_launch(void* const* d_in, const int* in_sizes, int n_in,
                              void* d_out, int out_size)
{
    const int*   inputs = (const int*)d_in[0];
    const float* hidden = (const float*)d_in[1];
    const float* emb    = (const float*)d_in[2];
    const float* Wx0    = (const float*)d_in[3];
    const float* Wh0    = (const float*)d_in[4];
    const float* bh0    = (const float*)d_in[5];
    const float* Wy0    = (const float*)d_in[6];
    const float* by0    = (const float*)d_in[7];
    const float* Wx1    = (const float*)d_in[8];
    const float* Wh1    = (const float*)d_in[9];
    const float* bh1    = (const float*)d_in[10];
    const float* Wy1    = (const float*)d_in[11];
    const float* by1    = (const float*)d_in[12];
    float* out = (float*)d_out;

    (void)in_sizes; (void)n_in; (void)out_size;

    static int attr_done = 0;
    if (!attr_done) {
        cudaFuncSetAttribute(recur_kernel,
                             cudaFuncAttributeMaxDynamicSharedMemorySize, SMEM_DYN_BYTES);
        attr_done = 1;
    }

    // 1) reset grid barrier
    init_bar_kernel<<<1, 1>>>();
    // 2) pre-split Wy1 (independent of recurrence)
    preconvB_kernel<<<NPAD, 256>>>(Wy1);
    // 3) sequential recurrence (bit-exact XLA:CPU emulation)
    recur_kernel<<<128, 256, SMEM_DYN_BYTES>>>(inputs, hidden, emb,
                                               Wx0, Wh0, bh0, Wy0, by0,
                                               Wx1, Wh1, bh1, out);
    // 4) pre-split h1 activations
    preconvA_kernel<<<S_ * B_, 256>>>();
    // 5) logits GEMM on tensor cores (HMMA via mma.sync, bf16 2-term split)
    gemm_bf16_kernel<<<dim3(NPAD / 128, 32), 256>>>(by1, out);
}

// round 11
// speedup vs baseline: 3.2500x; 1.0109x over previous
#include <cuda_runtime.h>
#include <cuda_bf16.h>
#include <cstdint>

#define S_ 64
#define B_ 64
#define V_ 10000
#define E_ 256
#define H_ 512

#define KSPLIT 1536           // K' = 3*H : [hi|hi|lo] x [hi|lo|hi]
#define NPAD   10112          // 79 tiles of 128

// ---------------- device scratch (static: no allocations allowed) ----------------
__device__ float g_h0[B_ * H_];
__device__ float g_y0[B_ * H_];
__device__ float g_h1all[S_ * B_ * H_];
__device__ unsigned g_bar_cnt;
__device__ volatile unsigned g_bar_gen;

// bf16 split operands for the logits GEMM (A'' 12.6MB, B'' 31.1MB)
__device__ __nv_bfloat16 g_A2[(size_t)S_ * B_ * KSPLIT];
__device__ __nv_bfloat16 g_B2[(size_t)NPAD * KSPLIT];

// ---------------- XLA/Eigen fast-tanh clone (bit-exact vs reference) ----------------
// DO NOT TOUCH: recurrence trajectory is bit-exact vs XLA:CPU (amplifies ~2e4x).
__device__ __forceinline__ float tanh_xla(float x)
{
    if (fabsf(x) < 0.0004f) return x;
    float xc = fminf(fmaxf(x, -9.0f), 9.0f);
    float x2 = xc * xc;
    float a = -2.76076847742355e-16f;
    a = __fmaf_rn(a, x2, 2.00018790482477e-13f);
    a = __fmaf_rn(a, x2, -8.60467152213735e-11f);
    a = __fmaf_rn(a, x2, 5.12229709037114e-08f);
    a = __fmaf_rn(a, x2, 1.48572235717979e-05f);
    a = __fmaf_rn(a, x2, 6.37261928875436e-04f);
    a = __fmaf_rn(a, x2, 4.89352455891786e-03f);
    float num = xc * a;
    float q = 1.19825839466702e-06f;
    q = __fmaf_rn(q, x2, 1.18534705686654e-04f);
    q = __fmaf_rn(q, x2, 2.26843463243900e-03f);
    q = __fmaf_rn(q, x2, 4.89352518554385e-03f);
    return __fdiv_rn(num, q);
}

// ---------------- grid barrier (proven) --------------------------------------------
__device__ __forceinline__ void grid_bar(unsigned epoch)
{
    __syncthreads();
    if (threadIdx.x == 0) {
        __threadfence();
        unsigned prev = atomicAdd(&g_bar_cnt, 1u);
        if (prev == gridDim.x - 1u) {
            atomicExch(&g_bar_cnt, 0u);
            __threadfence();
            g_bar_gen = epoch;
        } else {
            while (g_bar_gen < epoch) { }
            __threadfence();
        }
    }
    __syncthreads();
}

__global__ void init_bar_kernel()
{
    g_bar_cnt = 0u;
    g_bar_gen = 0u;
}

// ---------------- cp.async helpers -------------------------------------------------
#define CPA16(dst, src) asm volatile("cp.async.cg.shared.global [%0], [%1], 16;" :: "r"(dst), "l"(src) : "memory")
#define CPC()  asm volatile("cp.async.commit_group;" ::: "memory")
#define CPW1() asm volatile("cp.async.wait_group 1;" ::: "memory")
#define CPW0() asm volatile("cp.async.wait_group 0;" ::: "memory")

__device__ __forceinline__ unsigned smem_u32(const void* p)
{
    return (unsigned)__cvta_generic_to_shared(p);
}

// ---------------- recurrence machinery (proven since round 8) -----------------------
#define SMEM_DYN_BYTES 143616
#define XA(i) (sm + (i) * 8448)
#define XB(i) (sm + 16896 + (i) * 8448)
#define WA(i) (sm + 33792 + (i) * 512)
#define WB(i) (sm + 34816 + (i) * 512)

__device__ __forceinline__ void stage_x(float* Xs, const float* base, int ck)
{
    int row = threadIdx.x >> 5, lane = threadIdx.x & 31;
#pragma unroll
    for (int i = 0; i < 8; i++) {
        int r = row + i * 8;
        unsigned dst = smem_u32(Xs + r * 132 + lane * 4);
        CPA16(dst, base + (size_t)r * H_ + ck * 128 + lane * 4);
    }
}

__device__ __forceinline__ void stage_emb(float* Xs, const float* emb, const int* sbp, int ck)
{
    int row = threadIdx.x >> 5, lane = threadIdx.x & 31;
#pragma unroll
    for (int i = 0; i < 8; i++) {
        int r = row + i * 8;
        unsigned dst = smem_u32(Xs + r * 132 + lane * 4);
        CPA16(dst, emb + (size_t)sbp[r] + ck * 128 + lane * 4);
    }
}

__device__ __forceinline__ void stage_w(float* Ws, const float* W, int len, int colbase, int ck)
{
    if (threadIdx.x < 128) {
        int row = threadIdx.x >> 5, lane = threadIdx.x & 31;
        unsigned dst = smem_u32(Ws + row * 128 + lane * 4);
        CPA16(dst, W + (size_t)(colbase + row) * len + ck * 128 + lane * 4);
    }
}

__device__ __forceinline__ float comp1(float acc, const float* Xs, const float* Ws,
                                       int b, int cj)
{
    const float4* xv = (const float4*)(Xs + b * 132);
    const float4* wv = (const float4*)(Ws + cj * 128);
#pragma unroll
    for (int k = 0; k < 32; k++) {
        float4 x = xv[k];
        float4 w = wv[k];
        acc = __fmaf_rn(x.x, w.x, acc);
        acc = __fmaf_rn(x.y, w.y, acc);
        acc = __fmaf_rn(x.z, w.z, acc);
        acc = __fmaf_rn(x.w, w.w, acc);
    }
    return acc;
}

__global__ __launch_bounds__(256, 1) void recur_kernel(
    const int* __restrict__ inputs, const float* __restrict__ hidden,
    const float* __restrict__ emb,
    const float* __restrict__ Wx0, const float* __restrict__ Wh0,
    const float* __restrict__ bh0,
    const float* __restrict__ Wy0, const float* __restrict__ by0,
    const float* __restrict__ Wx1, const float* __restrict__ Wh1,
    const float* __restrict__ bh1,
    float* __restrict__ out)
{
    extern __shared__ float sm[];
    int* sbp = (int*)(sm + 35840);
    int tid = threadIdx.x;
    int b = tid & 63;
    int cj = tid >> 6;
    int colbase = blockIdx.x * 4;
    int col = colbase + cj;
    float* out_states = out + (size_t)S_ * B_ * V_;
    unsigned epoch = 0;

    if (tid < 64) sbp[tid] = inputs[tid] * E_;
    __syncthreads();
    float d1 = 0.f;
    {
        stage_emb(XB(0), emb, sbp, 0);
        stage_w(WB(0), Wx0, E_, colbase, 0);
        CPC();
#pragma unroll
        for (int ck = 0; ck < 2; ck++) {
            if (ck < 1) {
                stage_emb(XB(1), emb, sbp, 1);
                stage_w(WB(1), Wx0, E_, colbase, 1);
                CPC(); CPW1();
            } else CPW0();
            __syncthreads();
            d1 = comp1(d1, XB(ck), WB(ck), b, cj);
            __syncthreads();
        }
    }

    for (int t = 0; t < S_; t++) {
        const float* P0 = (t == 0) ? hidden : (g_h1all + (size_t)(t - 1) * B_ * H_);
        float d2 = 0.f;
        stage_x(XA(0), P0, 0);
        stage_w(WA(0), Wh0, H_, colbase, 0);
        CPC();
#pragma unroll
        for (int ck = 0; ck < 4; ck++) {
            int cb = ck & 1, nb = (ck + 1) & 1;
            if (ck < 3) {
                stage_x(XA(nb), P0, ck + 1);
                stage_w(WA(nb), Wh0, H_, colbase, ck + 1);
                CPC(); CPW1();
            } else CPW0();
            __syncthreads();
            d2 = comp1(d2, XA(cb), WA(cb), b, cj);
            __syncthreads();
        }
        float h0v = tanh_xla((d1 + d2) + bh0[col]);
        g_h0[(size_t)b * H_ + col] = h0v;
        if (t == S_ - 1) out_states[(size_t)b * H_ + col] = h0v;
        grid_bar(++epoch);

        const float* P1 = (t == 0) ? (hidden + (size_t)B_ * H_) : g_h0;
        float dy = 0.f, e2 = 0.f;
        stage_x(XA(0), g_h0, 0);
        stage_x(XB(0), P1, 0);
        stage_w(WA(0), Wy0, H_, colbase, 0);
        stage_w(WB(0), Wh1, H_, colbase, 0);
        CPC();
#pragma unroll
        for (int ck = 0; ck < 4; ck++) {
            int cb = ck & 1, nb = (ck + 1) & 1;
            if (ck < 3) {
                stage_x(XA(nb), g_h0, ck + 1);
                stage_x(XB(nb), P1, ck + 1);
                stage_w(WA(nb), Wy0, H_, colbase, ck + 1);
                stage_w(WB(nb), Wh1, H_, colbase, ck + 1);
                CPC(); CPW1();
            } else CPW0();
            __syncthreads();
            dy = comp1(dy, XA(cb), WA(cb), b, cj);
            e2 = comp1(e2, XB(cb), WB(cb), b, cj);
            __syncthreads();
        }
        g_y0[(size_t)b * H_ + col] = dy + by0[col];
        if (t < S_ - 1 && tid < 64) sbp[tid] = inputs[(t + 1) * B_ + tid] * E_;
        grid_bar(++epoch);

        bool doemb = (t < S_ - 1);
        float e1 = 0.f, d1n = 0.f;
        stage_x(XA(0), g_y0, 0);
        stage_w(WA(0), Wx1, H_, colbase, 0);
        if (doemb) {
            stage_emb(XB(0), emb, sbp, 0);
            stage_w(WB(0), Wx0, E_, colbase, 0);
        }
        CPC();
#pragma unroll
        for (int ck = 0; ck < 4; ck++) {
            int cb = ck & 1, nb = (ck + 1) & 1;
            if (ck < 3) {
                stage_x(XA(nb), g_y0, ck + 1);
                stage_w(WA(nb), Wx1, H_, colbase, ck + 1);
                if (doemb && ck + 1 < 2) {
                    stage_emb(XB(nb), emb, sbp, ck + 1);
                    stage_w(WB(nb), Wx0, E_, colbase, ck + 1);
                }
                CPC(); CPW1();
            } else CPW0();
            __syncthreads();
            e1 = comp1(e1, XA(cb), WA(cb), b, cj);
            if (doemb && ck < 2) d1n = comp1(d1n, XB(cb), WB(cb), b, cj);
            __syncthreads();
        }
        float h1v = tanh_xla((e1 + e2) + bh1[col]);
        g_h1all[(size_t)t * B_ * H_ + (size_t)b * H_ + col] = h1v;
        // fused preconvA: write bf16 split row [hi | hi | lo] for the logits GEMM
        {
            __nv_bfloat16 hi = __float2bfloat16(h1v);
            __nv_bfloat16 lo = __float2bfloat16(h1v - __bfloat162float(hi));
            size_t arow = (size_t)(t * B_ + b) * KSPLIT;
            g_A2[arow + col] = hi;
            g_A2[arow + 512 + col] = hi;
            g_A2[arow + 1024 + col] = lo;
        }
        if (t == S_ - 1) out_states[(size_t)B_ * H_ + (size_t)b * H_ + col] = h1v;
        grid_bar(++epoch);
        d1 = d1n;
    }
}

// ---------------- B'' pre-conversion ------------------------------------------------
__global__ __launch_bounds__(256) void preconvB_kernel(const float* __restrict__ Wy1)
{
    int row = blockIdx.x;          // NPAD
    int t = threadIdx.x;
    float2 v = make_float2(0.f, 0.f);
    if (row < V_) v = ((const float2*)(Wy1 + (size_t)row * H_))[t];
    __nv_bfloat16 h0 = __float2bfloat16(v.x);
    __nv_bfloat16 h1 = __float2bfloat16(v.y);
    __nv_bfloat16 l0 = __float2bfloat16(v.x - __bfloat162float(h0));
    __nv_bfloat16 l1 = __float2bfloat16(v.y - __bfloat162float(h1));
    __nv_bfloat162 hh; hh.x = h0; hh.y = h1;
    __nv_bfloat162 ll; ll.x = l0; ll.y = l1;
    __nv_bfloat162* dst = (__nv_bfloat162*)(g_B2 + (size_t)row * KSPLIT);
    dst[t] = hh; dst[256 + t] = ll; dst[512 + t] = hh;
}

// ---------------- logits GEMM: HMMA + ldmatrix + K64 chunks -------------------------
// C[4096, 10000] = A''[4096,1536] @ B''[NPAD,1536]^T + bias.
// CTA 128x128, 8 warps (4x2), warp 32x64. K chunks of 64, cp.async double buffer.
// smem row stride 72 bf16 (144B): 16B-aligned cp.async, conflict-free ldmatrix phases.
#define GSTR 72
#define GEMM_SMEM 73728   // 2 mats * 2 bufs * 128 * 72 * 2B

__device__ __forceinline__ void mma16816(float* d, const unsigned* a, const unsigned* b)
{
    asm volatile(
        "mma.sync.aligned.m16n8k16.row.col.f32.bf16.bf16.f32 "
        "{%0,%1,%2,%3}, {%4,%5,%6,%7}, {%8,%9}, {%0,%1,%2,%3};"
        : "+f"(d[0]), "+f"(d[1]), "+f"(d[2]), "+f"(d[3])
        : "r"(a[0]), "r"(a[1]), "r"(a[2]), "r"(a[3]), "r"(b[0]), "r"(b[1]));
}

__device__ __forceinline__ void ldsm4(unsigned& r0, unsigned& r1, unsigned& r2,
                                      unsigned& r3, unsigned addr)
{
    asm volatile("ldmatrix.sync.aligned.m8n8.x4.shared.b16 {%0,%1,%2,%3}, [%4];"
                 : "=r"(r0), "=r"(r1), "=r"(r2), "=r"(r3) : "r"(addr));
}

__global__ __launch_bounds__(256, 2) void gemm_bf16_kernel(
    const float* __restrict__ bias, float* __restrict__ C)
{
    extern __shared__ char smg[];
    __nv_bfloat16* Asm0 = (__nv_bfloat16*)smg;            // [2][128*GSTR]
    __nv_bfloat16* Bsm0 = (__nv_bfloat16*)(smg + 36864);  // [2][128*GSTR]
    int tid = threadIdx.x, lane = tid & 31, wid = tid >> 5;
    int wm = wid & 3, wn = wid >> 2;
    int m0 = blockIdx.y * 128, n0 = blockIdx.x * 128;
    const __nv_bfloat16* Ag = g_A2 + (size_t)m0 * KSPLIT;
    const __nv_bfloat16* Bg = g_B2 + (size_t)n0 * KSPLIT;

    float acc[2][8][4];
#pragma unroll
    for (int i = 0; i < 2; i++)
#pragma unroll
        for (int j = 0; j < 8; j++)
#pragma unroll
            for (int k = 0; k < 4; k++) acc[i][j][k] = 0.f;

    // ldmatrix lane->element offsets (match the scalar-fragment layout verified in R10)
    // A (x4): lanes 0-15 -> rows R+lane @k+0 ; lanes 16-31 -> rows R+(lane-16) @k+8
    int aoff = (wm * 32 + (lane & 15)) * GSTR + (lane >> 4) * 8;
    // B (x4, n-pair): subs {n,k0},{n,k8},{n+8,k0},{n+8,k8}
    int bsub = lane >> 3;
    int boff = (wn * 64 + (bsub >> 1) * 8 + (lane & 7)) * GSTR + (bsub & 1) * 8;

#define STG64(buf, kc)                                                              \
    {                                                                               \
        _Pragma("unroll")                                                           \
        for (int i = 0; i < 4; i++) {                                               \
            int e = tid + i * 256;                                                  \
            int row = e >> 3, seg = e & 7;                                          \
            CPA16(smem_u32(Asm0 + (buf) * 9216 + row * GSTR + seg * 8),             \
                  Ag + (size_t)row * KSPLIT + (kc) * 64 + seg * 8);                 \
            CPA16(smem_u32(Bsm0 + (buf) * 9216 + row * GSTR + seg * 8),             \
                  Bg + (size_t)row * KSPLIT + (kc) * 64 + seg * 8);                 \
        }                                                                           \
    }

    STG64(0, 0); CPC();

    const int NCH = KSPLIT / 64;   // 24
    for (int kc = 0; kc < NCH; kc++) {
        int cur = kc & 1;
        if (kc < NCH - 1) { STG64(cur ^ 1, kc + 1); CPC(); CPW1(); }
        else CPW0();
        __syncthreads();

        unsigned abase = smem_u32(Asm0 + cur * 9216);
        unsigned bbase = smem_u32(Bsm0 + cur * 9216);
#pragma unroll
        for (int s = 0; s < 4; s++) {
            int kb = s * 16;
            unsigned afr[2][4], bfr[8][2];
#pragma unroll
            for (int mf = 0; mf < 2; mf++)
                ldsm4(afr[mf][0], afr[mf][1], afr[mf][2], afr[mf][3],
                      abase + (unsigned)(aoff + mf * 16 * GSTR + kb) * 2);
#pragma unroll
            for (int p = 0; p < 4; p++) {
                unsigned t0, t1, t2, t3;
                ldsm4(t0, t1, t2, t3,
                      bbase + (unsigned)(boff + p * 16 * GSTR + kb) * 2);
                bfr[2 * p][0] = t0; bfr[2 * p][1] = t1;
                bfr[2 * p + 1][0] = t2; bfr[2 * p + 1][1] = t3;
            }
#pragma unroll
            for (int mf = 0; mf < 2; mf++)
#pragma unroll
                for (int nf = 0; nf < 8; nf++)
                    mma16816(acc[mf][nf], afr[mf], bfr[nf]);
        }
        __syncthreads();
    }

    // epilogue (verified in R10): rows gr/gr+8, col pair (lane&3)*2 per frag
    int gr = lane >> 2, cn = (lane & 3) * 2;
#pragma unroll
    for (int mf = 0; mf < 2; mf++) {
        int r = m0 + wm * 32 + mf * 16 + gr;
#pragma unroll
        for (int nf = 0; nf < 8; nf++) {
            int c = n0 + wn * 64 + nf * 8 + cn;
            if (c < V_) {
                float2 b2 = *(const float2*)(bias + c);
                float2 o0, o1;
                o0.x = acc[mf][nf][0] + b2.x;
                o0.y = acc[mf][nf][1] + b2.y;
                o1.x = acc[mf][nf][2] + b2.x;
                o1.y = acc[mf][nf][3] + b2.y;
                *(float2*)(C + (size_t)r * V_ + c) = o0;
                *(float2*)(C + (size_t)(r + 8) * V_ + c) = o1;
            }
        }
    }
}

// ---------------- launch ----------------
extern "C" void kernel_launch(void* const* d_in, const int* in_sizes, int n_in,
                              void* d_out, int out_size)
{
    const int*   inputs = (const int*)d_in[0];
    const float* hidden = (const float*)d_in[1];
    const float* emb    = (const float*)d_in[2];
    const float* Wx0    = (const float*)d_in[3];
    const float* Wh0    = (const float*)d_in[4];
    const float* bh0    = (const float*)d_in[5];
    const float* Wy0    = (const float*)d_in[6];
    const float* by0    = (const float*)d_in[7];
    const float* Wx1    = (const float*)d_in[8];
    const float* Wh1    = (const float*)d_in[9];
    const float* bh1    = (const float*)d_in[10];
    const float* Wy1    = (const float*)d_in[11];
    const float* by1    = (const float*)d_in[12];
    float* out = (float*)d_out;

    (void)in_sizes; (void)n_in; (void)out_size;

    static int attr_done = 0;
    if (!attr_done) {
        cudaFuncSetAttribute(recur_kernel,
                             cudaFuncAttributeMaxDynamicSharedMemorySize, SMEM_DYN_BYTES);
        cudaFuncSetAttribute(gemm_bf16_kernel,
                             cudaFuncAttributeMaxDynamicSharedMemorySize, GEMM_SMEM);
        attr_done = 1;
    }

    // 1) reset grid barrier
    init_bar_kernel<<<1, 1>>>();
    // 2) pre-split Wy1 (independent of recurrence)
    preconvB_kernel<<<NPAD, 256>>>(Wy1);
    // 3) sequential recurrence (bit-exact XLA:CPU emulation) + fused A'' split
    recur_kernel<<<128, 256, SMEM_DYN_BYTES>>>(inputs, hidden, emb,
                                               Wx0, Wh0, bh0, Wy0, by0,
                                               Wx1, Wh1, bh1, out);
    // 4) logits GEMM on tensor cores (HMMA + ldmatrix, K64 double-buffered)
    gemm_bf16_kernel<<<dim3(NPAD / 128, 32), 256, GEMM_SMEM>>>(by1, out);
}